// round 7
// baseline (speedup 1.0000x reference)
#include <cuda_runtime.h>
#include <cuda_bf16.h>
#include <math.h>
#include <stdint.h>

#define BATCH 8
#define SEQ   2048
#define DIM   128
#define HDIM  128
#define MASK_VALUE -1e30f

// fp32 scratch for projected q
__device__ float g_q[BATCH * SEQ * HDIM];
// interleaved bf16-split K: per kv row, 8 ksteps x 4 t, uint4 = {hi_t, hi_t+4, lo_t, lo_t+4}
__device__ uint4 g_kint[BATCH * SEQ * 32];
// interleaved bf16-split V^T: per (b,d), 32 kv-tiles x (4 kk x 4 t) uint4
__device__ uint4 g_vint[BATCH * 128 * 512];

// ---------------- helpers ----------------
__device__ __forceinline__ void split2(float x, float y, uint32_t& hi, uint32_t& lo) {
    __nv_bfloat16 hx = __float2bfloat16(x), hy = __float2bfloat16(y);
    __nv_bfloat16 lx = __float2bfloat16(x - __bfloat162float(hx));
    __nv_bfloat16 ly = __float2bfloat16(y - __bfloat162float(hy));
    hi = ((uint32_t)__bfloat16_as_ushort(hy) << 16) | (uint32_t)__bfloat16_as_ushort(hx);
    lo = ((uint32_t)__bfloat16_as_ushort(ly) << 16) | (uint32_t)__bfloat16_as_ushort(lx);
}

__device__ __forceinline__ void mma16816(float* d, const uint32_t* a, const uint32_t* b) {
    asm volatile(
        "mma.sync.aligned.m16n8k16.row.col.f32.bf16.bf16.f32 "
        "{%0,%1,%2,%3}, {%4,%5,%6,%7}, {%8,%9}, {%0,%1,%2,%3};"
        : "+f"(d[0]), "+f"(d[1]), "+f"(d[2]), "+f"(d[3])
        : "r"(a[0]), "r"(a[1]), "r"(a[2]), "r"(a[3]), "r"(b[0]), "r"(b[1]));
}

__device__ __forceinline__ uint32_t smem_u32(const void* p) {
    uint32_t a;
    asm("{ .reg .u64 t; cvta.to.shared.u64 t, %1; cvt.u32.u64 %0, t; }" : "=r"(a) : "l"(p));
    return a;
}
__device__ __forceinline__ void cp16(uint32_t dst, const void* src) {
    asm volatile("cp.async.cg.shared.global [%0], [%1], 16;"
                 :: "r"(dst), "l"(__cvta_generic_to_global(src)) : "memory");
}
#define CP_COMMIT() asm volatile("cp.async.commit_group;" ::: "memory")
#define CP_WAIT1()  asm volatile("cp.async.wait_group 1;" ::: "memory")

// ---------------- projection GEMM (conflict-free); K epilogue writes
// interleaved split-bf16 directly via lane-pair shuffle ----------------
__global__ __launch_bounds__(256) void proj_kernel(const float* __restrict__ Xq,
                                                   const float* __restrict__ Xk,
                                                   const float* __restrict__ Wq,
                                                   const float* __restrict__ Wk) {
    __shared__ float As[8][128];
    __shared__ float Bs[8][128];
    const int tid = threadIdx.x, tx = tid & 15, ty = tid >> 4;
    const int m0 = blockIdx.x * 128;
    const int isK = (blockIdx.y != 0);
    const float* __restrict__ X = isK ? Xk : Xq;
    const float* __restrict__ W = isK ? Wk : Wq;
    float acc[8][8];
#pragma unroll
    for (int i = 0; i < 8; i++)
#pragma unroll
        for (int j = 0; j < 8; j++) acc[i][j] = 0.f;
    for (int k0 = 0; k0 < DIM; k0 += 8) {
        {
            const int row = tid >> 1, u = (tid & 1) * 4;
            float4 x = *(const float4*)&X[(size_t)(m0 + row) * DIM + k0 + u];
            As[u][row] = x.x; As[u + 1][row] = x.y; As[u + 2][row] = x.z; As[u + 3][row] = x.w;
        }
        {
            const int kk = tid >> 5, n0 = (tid & 31) * 4;
            *(float4*)&Bs[kk][n0] = *(const float4*)&W[(size_t)(k0 + kk) * HDIM + n0];
        }
        __syncthreads();
#pragma unroll
        for (int k = 0; k < 8; k++) {
            float ra[8], rb[8];
            *(float4*)&ra[0] = *(float4*)&As[k][ty * 8];
            *(float4*)&ra[4] = *(float4*)&As[k][ty * 8 + 4];
#pragma unroll
            for (int nn = 0; nn < 8; nn++) rb[nn] = Bs[k][tx + 16 * nn];
#pragma unroll
            for (int rr = 0; rr < 8; rr++)
#pragma unroll
                for (int nn = 0; nn < 8; nn++) acc[rr][nn] = fmaf(ra[rr], rb[nn], acc[rr][nn]);
        }
        __syncthreads();
    }
    if (!isK) {
#pragma unroll
        for (int rr = 0; rr < 8; rr++)
#pragma unroll
            for (int nn = 0; nn < 8; nn++)
                g_q[(size_t)(m0 + ty * 8 + rr) * HDIM + tx + 16 * nn] = acc[rr][nn];
    } else {
        // thread owns cols {tx + 16*nn}; lane tx^1 owns the paired column.
        uint32_t* kp = (uint32_t*)g_kint;
        const int r = tx >> 1, tt = r & 3, hp = r >> 2;
#pragma unroll
        for (int rr = 0; rr < 8; rr++) {
            const int m = m0 + ty * 8 + rr;
#pragma unroll
            for (int nn = 0; nn < 8; nn++) {
                const float x = acc[rr][nn];
                const float y = __shfl_xor_sync(0xffffffffu, x, 1);
                if (!(tx & 1)) {
                    uint32_t h, l;
                    split2(x, y, h, l);
                    const int u = (m * 8 + nn) * 16 + tt * 4 + hp;
                    kp[u] = h;
                    kp[u + 2] = l;
                }
            }
        }
    }
}

// ---------------- V: transpose + split -> interleaved g_vint ----------------
__global__ __launch_bounds__(256) void vprep_kernel(const float* __restrict__ Vg) {
    __shared__ float stg[64 * 132];
    const int tid = threadIdx.x;
    const int tile = blockIdx.x;      // 64-kv tile
    const int kv0 = tile * 64;
    const int b   = blockIdx.y;
#pragma unroll
    for (int it = 0; it < 8; it++) {
        const int u = tid + it * 256;
        const int row = u >> 5, c4 = (u & 31) * 4;
        *(float4*)&stg[row * 132 + c4] =
            *(const float4*)&Vg[(size_t)(b * SEQ + kv0 + row) * DIM + c4];
    }
    __syncthreads();
    const int d = tid & 127, half = tid >> 7;
    uint32_t* vp = (uint32_t*)g_vint;
#pragma unroll
    for (int i = 0; i < 16; i++) {
        const int w = half * 16 + i;               // kv word within tile (0..31)
        uint32_t h, l;
        split2(stg[(2 * w) * 132 + d], stg[(2 * w + 1) * 132 + d], h, l);
        const int kk = w >> 3, r = w & 7, tt = r & 3, hp = r >> 2;
        const int u = (((b * 128 + d) * 32 + tile) * 16 + kk * 4 + tt) * 4 + hp;
        vp[u] = h;
        vp[u + 2] = l;
    }
}

// ---------------- fused flash attention, double-buffered cp.async ----------
// Q rows 576 B (36 uint4), K rows 576 B, V rows 320 B: all ≡64 mod 128 -> CF
#define SQ    0
#define QROW  576
#define SBUF  73728
#define KROW  576
#define OV    36864
#define VROW  320
#define BUFSZ 77824
#define SMSK  229376      // + cur*256
#define SM_TOTAL 229888

extern __shared__ __align__(16) char smx[];

__device__ __forceinline__ void prefetch_tile(uint32_t bufb, uint32_t mskb,
                                              const float* mb, int b, int it,
                                              int tid) {
    const int kv0 = it * 64;
#pragma unroll
    for (int u8 = 0; u8 < 8; u8++) {           // K: 2048 uint4
        const int u = tid + u8 * 256;
        const int row = u >> 5, c = u & 31;
        cp16(bufb + row * KROW + c * 16, &g_kint[(b * SEQ + kv0 + row) * 32 + c]);
    }
#pragma unroll
    for (int u8 = 0; u8 < 8; u8++) {           // V: 2048 uint4
        const int u = tid + u8 * 256;
        const int row = u >> 4, c = u & 15;
        cp16(bufb + OV + row * VROW + c * 16,
             &g_vint[((b * 128 + row) * 32 + it) * 16 + c]);
    }
    if (tid < 16) cp16(mskb + tid * 16, mb + kv0 + tid * 4);
}

__global__ void __launch_bounds__(256, 1)
attn_hmma(const float* __restrict__ maskg, float* __restrict__ Outg) {
    const int tid = threadIdx.x, lane = tid & 31, w = tid >> 5;
    const int g = lane >> 2, t = lane & 3;
    const int b = blockIdx.y, q0 = blockIdx.x * 128;
    const uint32_t sb = smem_u32(smx);

    const float* mb = maskg + (size_t)b * SEQ;

    // kick off first K/V prefetch before Q staging (independent)
    prefetch_tile(sb + SBUF, sb + SMSK, mb, b, 0, tid);
    CP_COMMIT();

    // ---- load + split Q tile (128 x 128) into interleaved layout ----
    {
        uint32_t* Qs32 = (uint32_t*)(smx + SQ);
        const float2* q2 = (const float2*)(g_q + ((size_t)b * SEQ + q0) * HDIM);
#pragma unroll
        for (int it = 0; it < 32; it++) {
            const int i = tid + it * 256;              // 8192 words
            const int row = i >> 6, wd = i & 63;
            const float2 v = q2[row * 64 + wd];
            uint32_t h, l;
            split2(v.x, v.y, h, l);
            const int ks = wd >> 3, r = wd & 7, tt = r & 3, hp = r >> 2;
            const int u = row * 144 + (ks * 4 + tt) * 4 + hp;
            Qs32[u] = h;
            Qs32[u + 2] = l;
        }
    }

    const int rg = w * 16 + g;
    const char* qbase = smx + SQ + rg * QROW + t * 16;

    float oacc[16][4];
#pragma unroll
    for (int n = 0; n < 16; n++)
#pragma unroll
        for (int i = 0; i < 4; i++) oacc[n][i] = 0.f;
    float m0 = -INFINITY, m1 = -INFINITY, l0 = 0.f, l1 = 0.f;

    for (int it = 0; it < SEQ / 64; it++) {
        const int cur = it & 1;
        __syncthreads();   // (A) everyone done reading buf[cur^1]
        if (it + 1 < SEQ / 64)
            prefetch_tile(sb + SBUF + (cur ^ 1) * BUFSZ,
                          sb + SMSK + (cur ^ 1) * 256, mb, b, it + 1, tid);
        CP_COMMIT();
        CP_WAIT1();        // buf[cur] landed
        __syncthreads();   // (B) all threads' copies visible

        const char* Kp = smx + SBUF + cur * BUFSZ;
        const char* Vp = Kp + OV;
        const float* ms = (const float*)(smx + SMSK + cur * 256);

        // ---- S = Q K^T (16 x 64 per warp), 3-product bf16 emulation ----
        float sacc[8][4];
#pragma unroll
        for (int j = 0; j < 8; j++)
#pragma unroll
            for (int i = 0; i < 4; i++) sacc[j][i] = 0.f;

#pragma unroll
        for (int ks = 0; ks < 8; ks++) {
            const uint4 a0 = *(const uint4*)(qbase + ks * 64);
            const uint4 a1 = *(const uint4*)(qbase + 8 * QROW + ks * 64);
            uint32_t ah[4] = {a0.x, a1.x, a0.y, a1.y};
            uint32_t al[4] = {a0.z, a1.z, a0.w, a1.w};
#pragma unroll
            for (int j = 0; j < 8; j++) {
                const uint4 kb = *(const uint4*)(Kp + (j * 8 + g) * KROW + ks * 64 + t * 16);
                uint32_t bh[2] = {kb.x, kb.y};
                uint32_t bl[2] = {kb.z, kb.w};
                mma16816(sacc[j], ah, bh);
                mma16816(sacc[j], ah, bl);
                mma16816(sacc[j], al, bh);
            }
        }

        // ---- mask + online softmax ----
        float rmax0 = -INFINITY, rmax1 = -INFINITY;
#pragma unroll
        for (int j = 0; j < 8; j++) {
            const float mva = ms[j * 8 + t * 2], mvb = ms[j * 8 + t * 2 + 1];
            sacc[j][0] = mva * sacc[j][0] + (1.f - mva) * MASK_VALUE;
            sacc[j][1] = mvb * sacc[j][1] + (1.f - mvb) * MASK_VALUE;
            sacc[j][2] = mva * sacc[j][2] + (1.f - mva) * MASK_VALUE;
            sacc[j][3] = mvb * sacc[j][3] + (1.f - mvb) * MASK_VALUE;
            rmax0 = fmaxf(rmax0, fmaxf(sacc[j][0], sacc[j][1]));
            rmax1 = fmaxf(rmax1, fmaxf(sacc[j][2], sacc[j][3]));
        }
#pragma unroll
        for (int off = 1; off <= 2; off <<= 1) {
            rmax0 = fmaxf(rmax0, __shfl_xor_sync(0xffffffffu, rmax0, off));
            rmax1 = fmaxf(rmax1, __shfl_xor_sync(0xffffffffu, rmax1, off));
        }
        const float mn0 = fmaxf(m0, rmax0), mn1 = fmaxf(m1, rmax1);
        const float a0 = __expf(m0 - mn0), a1 = __expf(m1 - mn1);
        float ps0 = 0.f, ps1 = 0.f;
#pragma unroll
        for (int j = 0; j < 8; j++) {
            sacc[j][0] = __expf(sacc[j][0] - mn0);
            sacc[j][1] = __expf(sacc[j][1] - mn0);
            sacc[j][2] = __expf(sacc[j][2] - mn1);
            sacc[j][3] = __expf(sacc[j][3] - mn1);
            ps0 += sacc[j][0] + sacc[j][1];
            ps1 += sacc[j][2] + sacc[j][3];
        }
#pragma unroll
        for (int off = 1; off <= 2; off <<= 1) {
            ps0 += __shfl_xor_sync(0xffffffffu, ps0, off);
            ps1 += __shfl_xor_sync(0xffffffffu, ps1, off);
        }
        l0 = l0 * a0 + ps0; m0 = mn0;
        l1 = l1 * a1 + ps1; m1 = mn1;
#pragma unroll
        for (int n = 0; n < 16; n++) {
            oacc[n][0] *= a0; oacc[n][1] *= a0;
            oacc[n][2] *= a1; oacc[n][3] *= a1;
        }

        // ---- O += P V (P frags straight from sacc registers) ----
#pragma unroll
        for (int kk = 0; kk < 4; kk++) {
            const int j0 = 2 * kk, j1 = 2 * kk + 1;
            uint32_t pah[4], pal[4];
            split2(sacc[j0][0], sacc[j0][1], pah[0], pal[0]);
            split2(sacc[j0][2], sacc[j0][3], pah[1], pal[1]);
            split2(sacc[j1][0], sacc[j1][1], pah[2], pal[2]);
            split2(sacc[j1][2], sacc[j1][3], pah[3], pal[3]);
#pragma unroll
            for (int n = 0; n < 16; n++) {
                const uint4 vv = *(const uint4*)(Vp + (n * 8 + g) * VROW + kk * 64 + t * 16);
                uint32_t bh[2] = {vv.x, vv.y};
                uint32_t bl[2] = {vv.z, vv.w};
                mma16816(oacc[n], pah, bh);
                mma16816(oacc[n], pah, bl);
                mma16816(oacc[n], pal, bh);
            }
        }
    }

    // ---- epilogue ----
    const float i0 = (l0 > 0.f) ? (1.f / l0) : 0.f;
    const float i1 = (l1 > 0.f) ? (1.f / l1) : 0.f;
    float2* o2a = (float2*)(Outg + ((size_t)b * SEQ + q0 + rg) * DIM);
    float2* o2b = (float2*)(Outg + ((size_t)b * SEQ + q0 + rg + 8) * DIM);
#pragma unroll
    for (int n = 0; n < 16; n++) {
        o2a[n * 4 + t] = make_float2(oacc[n][0] * i0, oacc[n][1] * i0);
        o2b[n * 4 + t] = make_float2(oacc[n][2] * i1, oacc[n][3] * i1);
    }
}

// ---------------------------------------------------------------------------
extern "C" void kernel_launch(void* const* d_in, const int* in_sizes, int n_in,
                              void* d_out, int out_size) {
    (void)in_sizes; (void)n_in; (void)out_size;
    const float* query = (const float*)d_in[0];
    const float* key   = (const float*)d_in[1];
    const float* value = (const float*)d_in[2];
    const float* mask  = (const float*)d_in[3];
    const float* Wq    = (const float*)d_in[4];
    const float* Wk    = (const float*)d_in[5];
    float* out = (float*)d_out;

    cudaFuncSetAttribute(attn_hmma, cudaFuncAttributeMaxDynamicSharedMemorySize, SM_TOTAL);

    proj_kernel<<<dim3(BATCH * SEQ / 128, 2), 256>>>(query, key, Wq, Wk);
    vprep_kernel<<<dim3(SEQ / 64, BATCH), 256>>>(value);
    attn_hmma<<<dim3(SEQ / 128, BATCH), 256, SM_TOTAL>>>(mask, out);
}

// round 9
// speedup vs baseline: 1.0639x; 1.0639x over previous
#include <cuda_runtime.h>
#include <cuda_bf16.h>
#include <math.h>
#include <stdint.h>

#define BATCH 8
#define SEQ   2048
#define DIM   128
#define HDIM  128
#define MASK_VALUE -1e30f
#define LOG2E 1.4426950408889634f

// fp32 scratch for projected q
__device__ float g_q[BATCH * SEQ * HDIM];
// interleaved bf16-split K: per kv row, 8 ksteps x 4 t, uint4 = {hi_t, hi_t+4, lo_t, lo_t+4}
__device__ uint4 g_kint[BATCH * SEQ * 32];
// interleaved bf16-split V^T: per (b,d), 32 kv64-tiles x (4 kk x 4 t) uint4
__device__ uint4 g_vint[BATCH * 128 * 512];

// ---------------- helpers ----------------
__device__ __forceinline__ void split2(float x, float y, uint32_t& hi, uint32_t& lo) {
    __nv_bfloat16 hx = __float2bfloat16(x), hy = __float2bfloat16(y);
    __nv_bfloat16 lx = __float2bfloat16(x - __bfloat162float(hx));
    __nv_bfloat16 ly = __float2bfloat16(y - __bfloat162float(hy));
    hi = ((uint32_t)__bfloat16_as_ushort(hy) << 16) | (uint32_t)__bfloat16_as_ushort(hx);
    lo = ((uint32_t)__bfloat16_as_ushort(ly) << 16) | (uint32_t)__bfloat16_as_ushort(lx);
}

__device__ __forceinline__ void mma16816(float* d, const uint32_t* a, const uint32_t* b) {
    asm volatile(
        "mma.sync.aligned.m16n8k16.row.col.f32.bf16.bf16.f32 "
        "{%0,%1,%2,%3}, {%4,%5,%6,%7}, {%8,%9}, {%0,%1,%2,%3};"
        : "+f"(d[0]), "+f"(d[1]), "+f"(d[2]), "+f"(d[3])
        : "r"(a[0]), "r"(a[1]), "r"(a[2]), "r"(a[3]), "r"(b[0]), "r"(b[1]));
}

__device__ __forceinline__ uint32_t smem_u32(const void* p) {
    uint32_t a;
    asm("{ .reg .u64 t; cvta.to.shared.u64 t, %1; cvt.u32.u64 %0, t; }" : "=r"(a) : "l"(p));
    return a;
}
__device__ __forceinline__ void cp16(uint32_t dst, const void* src) {
    asm volatile("cp.async.cg.shared.global [%0], [%1], 16;"
                 :: "r"(dst), "l"(__cvta_generic_to_global(src)) : "memory");
}
__device__ __forceinline__ float ex2f(float x) {
    float y;
    asm("ex2.approx.f32 %0, %1;" : "=f"(y) : "f"(x));
    return y;
}
#define MBAR_INIT(a, c) asm volatile("mbarrier.init.shared.b64 [%0], %1;" :: "r"(a), "r"(c) : "memory")
#define MBAR_ARRIVE(a)  asm volatile("mbarrier.arrive.shared.b64 _, [%0];" :: "r"(a) : "memory")
// .noinc: consume the init count instead of incrementing pend-count (round-8 deadlock fix)
#define CPASYNC_MBAR_ARRIVE(a) \
    asm volatile("cp.async.mbarrier.arrive.noinc.shared::cta.b64 [%0];" :: "r"(a) : "memory")

__device__ __forceinline__ void mbar_wait(uint32_t a, uint32_t ph) {
    asm volatile("{\n\t.reg .pred P;\n\tLW%=:\n\t"
                 "mbarrier.try_wait.parity.acquire.cta.shared::cta.b64 P, [%0], %1, 0x989680;\n\t"
                 "@!P bra LW%=;\n\t}" :: "r"(a), "r"(ph) : "memory");
}

// ---------------- projection GEMM (round-7, proven) ----------------
__global__ __launch_bounds__(256) void proj_kernel(const float* __restrict__ Xq,
                                                   const float* __restrict__ Xk,
                                                   const float* __restrict__ Wq,
                                                   const float* __restrict__ Wk) {
    __shared__ float As[8][128];
    __shared__ float Bs[8][128];
    const int tid = threadIdx.x, tx = tid & 15, ty = tid >> 4;
    const int m0 = blockIdx.x * 128;
    const int isK = (blockIdx.y != 0);
    const float* __restrict__ X = isK ? Xk : Xq;
    const float* __restrict__ W = isK ? Wk : Wq;
    float acc[8][8];
#pragma unroll
    for (int i = 0; i < 8; i++)
#pragma unroll
        for (int j = 0; j < 8; j++) acc[i][j] = 0.f;
    for (int k0 = 0; k0 < DIM; k0 += 8) {
        {
            const int row = tid >> 1, u = (tid & 1) * 4;
            float4 x = *(const float4*)&X[(size_t)(m0 + row) * DIM + k0 + u];
            As[u][row] = x.x; As[u + 1][row] = x.y; As[u + 2][row] = x.z; As[u + 3][row] = x.w;
        }
        {
            const int kk = tid >> 5, n0 = (tid & 31) * 4;
            *(float4*)&Bs[kk][n0] = *(const float4*)&W[(size_t)(k0 + kk) * HDIM + n0];
        }
        __syncthreads();
#pragma unroll
        for (int k = 0; k < 8; k++) {
            float ra[8], rb[8];
            *(float4*)&ra[0] = *(float4*)&As[k][ty * 8];
            *(float4*)&ra[4] = *(float4*)&As[k][ty * 8 + 4];
#pragma unroll
            for (int nn = 0; nn < 8; nn++) rb[nn] = Bs[k][tx + 16 * nn];
#pragma unroll
            for (int rr = 0; rr < 8; rr++)
#pragma unroll
                for (int nn = 0; nn < 8; nn++) acc[rr][nn] = fmaf(ra[rr], rb[nn], acc[rr][nn]);
        }
        __syncthreads();
    }
    if (!isK) {
#pragma unroll
        for (int rr = 0; rr < 8; rr++)
#pragma unroll
            for (int nn = 0; nn < 8; nn++)
                g_q[(size_t)(m0 + ty * 8 + rr) * HDIM + tx + 16 * nn] = acc[rr][nn];
    } else {
        uint32_t* kp = (uint32_t*)g_kint;
        const int r = tx >> 1, tt = r & 3, hp = r >> 2;
#pragma unroll
        for (int rr = 0; rr < 8; rr++) {
            const int m = m0 + ty * 8 + rr;
#pragma unroll
            for (int nn = 0; nn < 8; nn++) {
                const float x = acc[rr][nn];
                const float y = __shfl_xor_sync(0xffffffffu, x, 1);
                if (!(tx & 1)) {
                    uint32_t h, l;
                    split2(x, y, h, l);
                    const int u = (m * 8 + nn) * 16 + tt * 4 + hp;
                    kp[u] = h;
                    kp[u + 2] = l;
                }
            }
        }
    }
}

// ---------------- V: transpose + split -> interleaved g_vint ----------------
__global__ __launch_bounds__(256) void vprep_kernel(const float* __restrict__ Vg) {
    __shared__ float stg[64 * 132];
    const int tid = threadIdx.x;
    const int tile = blockIdx.x;
    const int kv0 = tile * 64;
    const int b   = blockIdx.y;
#pragma unroll
    for (int it = 0; it < 8; it++) {
        const int u = tid + it * 256;
        const int row = u >> 5, c4 = (u & 31) * 4;
        *(float4*)&stg[row * 132 + c4] =
            *(const float4*)&Vg[(size_t)(b * SEQ + kv0 + row) * DIM + c4];
    }
    __syncthreads();
    const int d = tid & 127, half = tid >> 7;
    uint32_t* vp = (uint32_t*)g_vint;
#pragma unroll
    for (int i = 0; i < 16; i++) {
        const int w = half * 16 + i;
        uint32_t h, l;
        split2(stg[(2 * w) * 132 + d], stg[(2 * w + 1) * 132 + d], h, l);
        const int kk = w >> 3, r = w & 7, tt = r & 3, hp = r >> 2;
        const int u = (((b * 128 + d) * 32 + tile) * 16 + kk * 4 + tt) * 4 + hp;
        vp[u] = h;
        vp[u + 2] = l;
    }
}

// ---------------- fused flash attention: mbarrier ring, no block barriers ---
// BN=32, 4 stages. Stage: K 32x576B (18432) + V 128x192B (24576) + mask 128B.
#define RING  4
#define NT    (SEQ / 32)
#define SSTR  43136
#define OVS   18432
#define OMS   43008
#define SMB   (RING * SSTR)       // 172544: mbarriers (full[4], empty[4])
#define SM_TOTAL 172672

extern __shared__ __align__(16) char smx[];

__global__ void __launch_bounds__(256, 1)
attn_hmma(const float* __restrict__ maskg, float* __restrict__ Outg) {
    const int tid = threadIdx.x, lane = tid & 31, w = tid >> 5;
    const int g = lane >> 2, t = lane & 3;
    const int b = blockIdx.y, q0 = blockIdx.x * 128;
    const uint32_t sb = smem_u32(smx);
    const uint32_t fullb = sb + SMB, emptyb = sb + SMB + 32;
    const float* mb = maskg + (size_t)b * SEQ;

    if (tid == 0) {
#pragma unroll
        for (int s = 0; s < RING; s++) {
            MBAR_INIT(fullb + s * 8, 256);
            MBAR_INIT(emptyb + s * 8, 256);
        }
    }
    __syncthreads();   // mbarrier init visible (only block barrier in kernel)

    // ---- prologue: fill stages 0..RING-2 ----
#pragma unroll
    for (int j = 0; j < RING - 1; j++) {
        const int kv0 = j * 32;
        const uint32_t stg = sb + j * SSTR;
#pragma unroll
        for (int u4 = 0; u4 < 4; u4++) {
            const int u = tid + u4 * 256;
            const int row = u >> 5, c = u & 31;
            cp16(stg + row * 576 + c * 16, &g_kint[(b * SEQ + kv0 + row) * 32 + c]);
        }
#pragma unroll
        for (int u4 = 0; u4 < 4; u4++) {
            const int u = tid + u4 * 256;
            const int row = u >> 3, c = u & 7;
            cp16(stg + OVS + row * 192 + c * 16,
                 &g_vint[((b * 128 + row) * 32 + (j >> 1)) * 16 + (j & 1) * 8 + c]);
        }
        if (tid < 8) cp16(stg + OMS + tid * 16, mb + kv0 + tid * 4);
        CPASYNC_MBAR_ARRIVE(fullb + j * 8);
    }

    // ---- Q fragments -> registers (rows rg, rg+8; 8 ksteps) ----
    const int rg = w * 16 + g;
    uint32_t qah[8][4], qal[8][4];
    {
        const float* q2a = g_q + ((size_t)b * SEQ + q0 + rg) * HDIM;
        const float* q2b = q2a + 8 * HDIM;
#pragma unroll
        for (int ks = 0; ks < 8; ks++) {
            const float2 x0 = *(const float2*)&q2a[ks * 16 + t * 2];
            const float2 x1 = *(const float2*)&q2b[ks * 16 + t * 2];
            const float2 x2 = *(const float2*)&q2a[ks * 16 + 8 + t * 2];
            const float2 x3 = *(const float2*)&q2b[ks * 16 + 8 + t * 2];
            split2(x0.x, x0.y, qah[ks][0], qal[ks][0]);
            split2(x1.x, x1.y, qah[ks][1], qal[ks][1]);
            split2(x2.x, x2.y, qah[ks][2], qal[ks][2]);
            split2(x3.x, x3.y, qah[ks][3], qal[ks][3]);
        }
    }

    float oacc[16][4];
#pragma unroll
    for (int n = 0; n < 16; n++)
#pragma unroll
        for (int i = 0; i < 4; i++) oacc[n][i] = 0.f;
    float m0 = -INFINITY, m1 = -INFINITY, l0 = 0.f, l1 = 0.f;

    for (int it = 0; it < NT; it++) {
        // ---- prefetch tile it+RING-1 ----
        const int j = it + RING - 1;
        if (j < NT) {
            const int s2 = j & (RING - 1), r = j >> 2;
            if (r >= 1) mbar_wait(emptyb + s2 * 8, (r - 1) & 1);
            const int kv0 = j * 32;
            const uint32_t stg = sb + s2 * SSTR;
#pragma unroll
            for (int u4 = 0; u4 < 4; u4++) {
                const int u = tid + u4 * 256;
                const int row = u >> 5, c = u & 31;
                cp16(stg + row * 576 + c * 16, &g_kint[(b * SEQ + kv0 + row) * 32 + c]);
            }
#pragma unroll
            for (int u4 = 0; u4 < 4; u4++) {
                const int u = tid + u4 * 256;
                const int row = u >> 3, c = u & 7;
                cp16(stg + OVS + row * 192 + c * 16,
                     &g_vint[((b * 128 + row) * 32 + (j >> 1)) * 16 + (j & 1) * 8 + c]);
            }
            if (tid < 8) cp16(stg + OMS + tid * 16, mb + kv0 + tid * 4);
            CPASYNC_MBAR_ARRIVE(fullb + s2 * 8);
        }

        // ---- consume tile it ----
        const int s = it & (RING - 1), rr = it >> 2;
        mbar_wait(fullb + s * 8, rr & 1);
        const char* Kp = smx + s * SSTR;
        const char* Vp = Kp + OVS;
        const float* ms = (const float*)(Kp + OMS);

        // S = Q K^T (16 x 32 per warp)
        float sacc[4][4];
#pragma unroll
        for (int j2 = 0; j2 < 4; j2++)
#pragma unroll
            for (int i = 0; i < 4; i++) sacc[j2][i] = 0.f;
#pragma unroll
        for (int ks = 0; ks < 8; ks++) {
#pragma unroll
            for (int j2 = 0; j2 < 4; j2++) {
                const uint4 kb = *(const uint4*)(Kp + (j2 * 8 + g) * 576 + ks * 64 + t * 16);
                uint32_t bh[2] = {kb.x, kb.y};
                uint32_t bl[2] = {kb.z, kb.w};
                mma16816(sacc[j2], qah[ks], bh);
                mma16816(sacc[j2], qah[ks], bl);
                mma16816(sacc[j2], qal[ks], bh);
            }
        }

        // mask + online softmax (rows g and g+8)
        float rmax0 = -INFINITY, rmax1 = -INFINITY;
#pragma unroll
        for (int j2 = 0; j2 < 4; j2++) {
            const float mva = ms[j2 * 8 + t * 2], mvb = ms[j2 * 8 + t * 2 + 1];
            sacc[j2][0] = mva * sacc[j2][0] + (1.f - mva) * MASK_VALUE;
            sacc[j2][1] = mvb * sacc[j2][1] + (1.f - mvb) * MASK_VALUE;
            sacc[j2][2] = mva * sacc[j2][2] + (1.f - mva) * MASK_VALUE;
            sacc[j2][3] = mvb * sacc[j2][3] + (1.f - mvb) * MASK_VALUE;
            rmax0 = fmaxf(rmax0, fmaxf(sacc[j2][0], sacc[j2][1]));
            rmax1 = fmaxf(rmax1, fmaxf(sacc[j2][2], sacc[j2][3]));
        }
#pragma unroll
        for (int off = 1; off <= 2; off <<= 1) {
            rmax0 = fmaxf(rmax0, __shfl_xor_sync(0xffffffffu, rmax0, off));
            rmax1 = fmaxf(rmax1, __shfl_xor_sync(0xffffffffu, rmax1, off));
        }
        const float mn0 = fmaxf(m0, rmax0), mn1 = fmaxf(m1, rmax1);
        const float a0 = ex2f((m0 - mn0) * LOG2E), a1 = ex2f((m1 - mn1) * LOG2E);
        float ps0 = 0.f, ps1 = 0.f;
#pragma unroll
        for (int j2 = 0; j2 < 4; j2++) {
            sacc[j2][0] = ex2f((sacc[j2][0] - mn0) * LOG2E);
            sacc[j2][1] = ex2f((sacc[j2][1] - mn0) * LOG2E);
            sacc[j2][2] = ex2f((sacc[j2][2] - mn1) * LOG2E);
            sacc[j2][3] = ex2f((sacc[j2][3] - mn1) * LOG2E);
            ps0 += sacc[j2][0] + sacc[j2][1];
            ps1 += sacc[j2][2] + sacc[j2][3];
        }
#pragma unroll
        for (int off = 1; off <= 2; off <<= 1) {
            ps0 += __shfl_xor_sync(0xffffffffu, ps0, off);
            ps1 += __shfl_xor_sync(0xffffffffu, ps1, off);
        }
        l0 = l0 * a0 + ps0; m0 = mn0;
        l1 = l1 * a1 + ps1; m1 = mn1;
#pragma unroll
        for (int n = 0; n < 16; n++) {
            oacc[n][0] *= a0; oacc[n][1] *= a0;
            oacc[n][2] *= a1; oacc[n][3] *= a1;
        }

        // O += P V
#pragma unroll
        for (int kk = 0; kk < 2; kk++) {
            const int j0 = 2 * kk, j1 = 2 * kk + 1;
            uint32_t pah[4], pal[4];
            split2(sacc[j0][0], sacc[j0][1], pah[0], pal[0]);
            split2(sacc[j0][2], sacc[j0][3], pah[1], pal[1]);
            split2(sacc[j1][0], sacc[j1][1], pah[2], pal[2]);
            split2(sacc[j1][2], sacc[j1][3], pah[3], pal[3]);
#pragma unroll
            for (int n = 0; n < 16; n++) {
                const uint4 vv = *(const uint4*)(Vp + (n * 8 + g) * 192 + kk * 64 + t * 16);
                uint32_t bh[2] = {vv.x, vv.y};
                uint32_t bl[2] = {vv.z, vv.w};
                mma16816(oacc[n], pah, bh);
                mma16816(oacc[n], pah, bl);
                mma16816(oacc[n], pal, bh);
            }
        }

        MBAR_ARRIVE(emptyb + s * 8);
    }

    // ---- epilogue ----
    const float i0 = (l0 > 0.f) ? (1.f / l0) : 0.f;
    const float i1 = (l1 > 0.f) ? (1.f / l1) : 0.f;
    float2* o2a = (float2*)(Outg + ((size_t)b * SEQ + q0 + rg) * DIM);
    float2* o2b = (float2*)(Outg + ((size_t)b * SEQ + q0 + rg + 8) * DIM);
#pragma unroll
    for (int n = 0; n < 16; n++) {
        o2a[n * 4 + t] = make_float2(oacc[n][0] * i0, oacc[n][1] * i0);
        o2b[n * 4 + t] = make_float2(oacc[n][2] * i1, oacc[n][3] * i1);
    }
}

// ---------------------------------------------------------------------------
extern "C" void kernel_launch(void* const* d_in, const int* in_sizes, int n_in,
                              void* d_out, int out_size) {
    (void)in_sizes; (void)n_in; (void)out_size;
    const float* query = (const float*)d_in[0];
    const float* key   = (const float*)d_in[1];
    const float* value = (const float*)d_in[2];
    const float* mask  = (const float*)d_in[3];
    const float* Wq    = (const float*)d_in[4];
    const float* Wk    = (const float*)d_in[5];
    float* out = (float*)d_out;

    cudaFuncSetAttribute(attn_hmma, cudaFuncAttributeMaxDynamicSharedMemorySize, SM_TOTAL);

    proj_kernel<<<dim3(BATCH * SEQ / 128, 2), 256>>>(query, key, Wq, Wk);
    vprep_kernel<<<dim3(SEQ / 64, BATCH), 256>>>(value);
    attn_hmma<<<dim3(SEQ / 128, BATCH), 256, SM_TOTAL>>>(mask, out);
}

// round 10
// speedup vs baseline: 1.1523x; 1.0831x over previous
#include <cuda_runtime.h>
#include <cuda_bf16.h>
#include <math.h>
#include <stdint.h>

#define BATCH 8
#define SEQ   2048
#define DIM   128
#define HDIM  128
#define MASK_VALUE -1e30f
#define LOG2E 1.4426950408889634f

// fp32 scratch for projected q
__device__ float g_q[BATCH * SEQ * HDIM];
// interleaved bf16-split K: per kv row, 8 ksteps x 4 t, uint4 = {hi_t, hi_t+4, lo_t, lo_t+4}
__device__ uint4 g_kint[BATCH * SEQ * 32];
// interleaved bf16-split V^T: per (b,d), 32 kv64-tiles x (4 kk x 4 t) uint4
__device__ uint4 g_vint[BATCH * 128 * 512];

// ---------------- helpers ----------------
__device__ __forceinline__ void split2(float x, float y, uint32_t& hi, uint32_t& lo) {
    __nv_bfloat16 hx = __float2bfloat16(x), hy = __float2bfloat16(y);
    __nv_bfloat16 lx = __float2bfloat16(x - __bfloat162float(hx));
    __nv_bfloat16 ly = __float2bfloat16(y - __bfloat162float(hy));
    hi = ((uint32_t)__bfloat16_as_ushort(hy) << 16) | (uint32_t)__bfloat16_as_ushort(hx);
    lo = ((uint32_t)__bfloat16_as_ushort(ly) << 16) | (uint32_t)__bfloat16_as_ushort(lx);
}

__device__ __forceinline__ void mma16816(float* d, const uint32_t* a, const uint32_t* b) {
    asm volatile(
        "mma.sync.aligned.m16n8k16.row.col.f32.bf16.bf16.f32 "
        "{%0,%1,%2,%3}, {%4,%5,%6,%7}, {%8,%9}, {%0,%1,%2,%3};"
        : "+f"(d[0]), "+f"(d[1]), "+f"(d[2]), "+f"(d[3])
        : "r"(a[0]), "r"(a[1]), "r"(a[2]), "r"(a[3]), "r"(b[0]), "r"(b[1]));
}

__device__ __forceinline__ uint32_t smem_u32(const void* p) {
    uint32_t a;
    asm("{ .reg .u64 t; cvta.to.shared.u64 t, %1; cvt.u32.u64 %0, t; }" : "=r"(a) : "l"(p));
    return a;
}
__device__ __forceinline__ void cp16(uint32_t dst, const void* src) {
    asm volatile("cp.async.cg.shared.global [%0], [%1], 16;"
                 :: "r"(dst), "l"(__cvta_generic_to_global(src)) : "memory");
}
__device__ __forceinline__ float ex2f(float x) {
    float y;
    asm("ex2.approx.f32 %0, %1;" : "=f"(y) : "f"(x));
    return y;
}
#define MBAR_INIT(a, c) asm volatile("mbarrier.init.shared.b64 [%0], %1;" :: "r"(a), "r"(c) : "memory")
#define MBAR_ARRIVE(a)  asm volatile("mbarrier.arrive.shared.b64 _, [%0];" :: "r"(a) : "memory")
#define CPASYNC_MBAR_ARRIVE(a) \
    asm volatile("cp.async.mbarrier.arrive.noinc.shared::cta.b64 [%0];" :: "r"(a) : "memory")

__device__ __forceinline__ void mbar_wait(uint32_t a, uint32_t ph) {
    asm volatile("{\n\t.reg .pred P;\n\tLW%=:\n\t"
                 "mbarrier.try_wait.parity.acquire.cta.shared::cta.b64 P, [%0], %1, 0x989680;\n\t"
                 "@!P bra LW%=;\n\t}" :: "r"(a), "r"(ph) : "memory");
}

extern __shared__ __align__(16) char smx[];

// ---------------- fused prep: HMMA projection (blocks 0-255) + vprep (256-511)
// proj smem: W^T interleaved, 128 rows(h) x 576 B (same layout as attn K tiles)
#define PREP_SMEM 73728

__global__ void __launch_bounds__(256, 1)
prep_kernel(const float* __restrict__ Xq, const float* __restrict__ Xk,
            const float* __restrict__ Wq, const float* __restrict__ Wk,
            const float* __restrict__ Vg) {
    const int tid = threadIdx.x, lane = tid & 31, wid = tid >> 5;
    const int g = lane >> 2, t = lane & 3;
    const int bid = blockIdx.x;

    if (bid < 256) {
        // ======== projection GEMM via split-bf16 HMMA ========
        const int isK = (bid >= 128);
        const int m0 = (bid & 127) * 128;
        const float* __restrict__ X = isK ? Xk : Xq;
        const float* __restrict__ W = isK ? Wk : Wq;

        // stage W^T (split hi/lo, interleaved) into smem: row h, stride 576 B
        uint32_t* Ws = (uint32_t*)smx;
        for (int task = tid; task < 1024; task += 256) {
            const int h = task >> 3, ks = task & 7;
            uint32_t hi[8], lo[8];
#pragma unroll
            for (int p = 0; p < 8; p++) {
                const float x = W[(ks * 16 + 2 * p) * HDIM + h];
                const float y = W[(ks * 16 + 2 * p + 1) * HDIM + h];
                split2(x, y, hi[p], lo[p]);
            }
            uint32_t* basep = Ws + h * 144 + ks * 16;
#pragma unroll
            for (int tt = 0; tt < 4; tt++) {
                basep[tt * 4 + 0] = hi[tt];
                basep[tt * 4 + 1] = hi[tt + 4];
                basep[tt * 4 + 2] = lo[tt];
                basep[tt * 4 + 3] = lo[tt + 4];
            }
        }
        __syncthreads();

        // A fragments: X rows rg, rg+8 (like attn Q)
        const int rg = wid * 16 + g;
        uint32_t ah[8][4], al[8][4];
        {
            const float* xa = X + (size_t)(m0 + rg) * DIM;
            const float* xb = xa + 8 * DIM;
#pragma unroll
            for (int ks = 0; ks < 8; ks++) {
                const float2 x0 = *(const float2*)&xa[ks * 16 + t * 2];
                const float2 x1 = *(const float2*)&xb[ks * 16 + t * 2];
                const float2 x2 = *(const float2*)&xa[ks * 16 + 8 + t * 2];
                const float2 x3 = *(const float2*)&xb[ks * 16 + 8 + t * 2];
                split2(x0.x, x0.y, ah[ks][0], al[ks][0]);
                split2(x1.x, x1.y, ah[ks][1], al[ks][1]);
                split2(x2.x, x2.y, ah[ks][2], al[ks][2]);
                split2(x3.x, x3.y, ah[ks][3], al[ks][3]);
            }
        }

        float acc[16][4];
#pragma unroll
        for (int n = 0; n < 16; n++)
#pragma unroll
            for (int i = 0; i < 4; i++) acc[n][i] = 0.f;

#pragma unroll
        for (int ks = 0; ks < 8; ks++) {
#pragma unroll
            for (int n = 0; n < 16; n++) {
                const uint4 bb = *(const uint4*)(smx + (n * 8 + g) * 576 + ks * 64 + t * 16);
                uint32_t bh[2] = {bb.x, bb.y};
                uint32_t bl[2] = {bb.z, bb.w};
                mma16816(acc[n], ah[ks], bh);
                mma16816(acc[n], ah[ks], bl);
                mma16816(acc[n], al[ks], bh);
            }
        }

        if (!isK) {
            float2* oa = (float2*)(g_q + (size_t)(m0 + rg) * HDIM);
            float2* ob = (float2*)(g_q + (size_t)(m0 + rg + 8) * HDIM);
#pragma unroll
            for (int n = 0; n < 16; n++) {
                oa[n * 4 + t] = make_float2(acc[n][0], acc[n][1]);
                ob[n * 4 + t] = make_float2(acc[n][2], acc[n][3]);
            }
        } else {
            // cols n*8 + t*2 (+1): kstep = n>>1, word w = (n&1)*4 + t
            // uint4 c = kstep*4 + t, component n&1 (hi) / 2+(n&1) (lo)
            uint32_t* kp = (uint32_t*)g_kint;
#pragma unroll
            for (int n = 0; n < 16; n++) {
                uint32_t h0, lo0, h1, lo1;
                split2(acc[n][0], acc[n][1], h0, lo0);
                split2(acc[n][2], acc[n][3], h1, lo1);
                const int u0 = ((m0 + rg) * 8 + (n >> 1)) * 16 + t * 4 + (n & 1);
                const int u1 = ((m0 + rg + 8) * 8 + (n >> 1)) * 16 + t * 4 + (n & 1);
                kp[u0] = h0; kp[u0 + 2] = lo0;
                kp[u1] = h1; kp[u1 + 2] = lo1;
            }
        }
    } else {
        // ======== V transpose + split -> interleaved g_vint ========
        float* stg = (float*)smx;               // 64 x 132 fp32
        const int v = bid - 256;
        const int tile = v & 31, b = v >> 5;
        const int kv0 = tile * 64;
#pragma unroll
        for (int it = 0; it < 8; it++) {
            const int u = tid + it * 256;
            const int row = u >> 5, c4 = (u & 31) * 4;
            *(float4*)&stg[row * 132 + c4] =
                *(const float4*)&Vg[(size_t)(b * SEQ + kv0 + row) * DIM + c4];
        }
        __syncthreads();
        const int d = tid & 127, half = tid >> 7;
        uint32_t* vp = (uint32_t*)g_vint;
#pragma unroll
        for (int i = 0; i < 16; i++) {
            const int wv = half * 16 + i;
            uint32_t h, l;
            split2(stg[(2 * wv) * 132 + d], stg[(2 * wv + 1) * 132 + d], h, l);
            const int kk = wv >> 3, r = wv & 7, tt = r & 3, hp = r >> 2;
            const int u = (((b * 128 + d) * 32 + tile) * 16 + kk * 4 + tt) * 4 + hp;
            vp[u] = h;
            vp[u + 2] = l;
        }
    }
}

// ---------------- fused flash attention: mbarrier ring (round-9, proven) ----
#define RING  4
#define NT    (SEQ / 32)
#define SSTR  43136
#define OVS   18432
#define OMS   43008
#define SMB   (RING * SSTR)
#define SM_TOTAL 172672

__global__ void __launch_bounds__(256, 1)
attn_hmma(const float* __restrict__ maskg, float* __restrict__ Outg) {
    const int tid = threadIdx.x, lane = tid & 31, w = tid >> 5;
    const int g = lane >> 2, t = lane & 3;
    const int b = blockIdx.y, q0 = blockIdx.x * 128;
    const uint32_t sb = smem_u32(smx);
    const uint32_t fullb = sb + SMB, emptyb = sb + SMB + 32;
    const float* mb = maskg + (size_t)b * SEQ;

    if (tid == 0) {
#pragma unroll
        for (int s = 0; s < RING; s++) {
            MBAR_INIT(fullb + s * 8, 256);
            MBAR_INIT(emptyb + s * 8, 256);
        }
    }
    __syncthreads();

    // ---- prologue: fill stages 0..RING-2 ----
#pragma unroll
    for (int j = 0; j < RING - 1; j++) {
        const int kv0 = j * 32;
        const uint32_t stg = sb + j * SSTR;
#pragma unroll
        for (int u4 = 0; u4 < 4; u4++) {
            const int u = tid + u4 * 256;
            const int row = u >> 5, c = u & 31;
            cp16(stg + row * 576 + c * 16, &g_kint[(b * SEQ + kv0 + row) * 32 + c]);
        }
#pragma unroll
        for (int u4 = 0; u4 < 4; u4++) {
            const int u = tid + u4 * 256;
            const int row = u >> 3, c = u & 7;
            cp16(stg + OVS + row * 192 + c * 16,
                 &g_vint[((b * 128 + row) * 32 + (j >> 1)) * 16 + (j & 1) * 8 + c]);
        }
        if (tid < 8) cp16(stg + OMS + tid * 16, mb + kv0 + tid * 4);
        CPASYNC_MBAR_ARRIVE(fullb + j * 8);
    }

    // ---- Q fragments -> registers ----
    const int rg = w * 16 + g;
    uint32_t qah[8][4], qal[8][4];
    {
        const float* q2a = g_q + ((size_t)b * SEQ + q0 + rg) * HDIM;
        const float* q2b = q2a + 8 * HDIM;
#pragma unroll
        for (int ks = 0; ks < 8; ks++) {
            const float2 x0 = *(const float2*)&q2a[ks * 16 + t * 2];
            const float2 x1 = *(const float2*)&q2b[ks * 16 + t * 2];
            const float2 x2 = *(const float2*)&q2a[ks * 16 + 8 + t * 2];
            const float2 x3 = *(const float2*)&q2b[ks * 16 + 8 + t * 2];
            split2(x0.x, x0.y, qah[ks][0], qal[ks][0]);
            split2(x1.x, x1.y, qah[ks][1], qal[ks][1]);
            split2(x2.x, x2.y, qah[ks][2], qal[ks][2]);
            split2(x3.x, x3.y, qah[ks][3], qal[ks][3]);
        }
    }

    float oacc[16][4];
#pragma unroll
    for (int n = 0; n < 16; n++)
#pragma unroll
        for (int i = 0; i < 4; i++) oacc[n][i] = 0.f;
    float m0 = -INFINITY, m1 = -INFINITY, l0 = 0.f, l1 = 0.f;

    for (int it = 0; it < NT; it++) {
        // ---- prefetch tile it+RING-1 ----
        const int j = it + RING - 1;
        if (j < NT) {
            const int s2 = j & (RING - 1), r = j >> 2;
            if (r >= 1) mbar_wait(emptyb + s2 * 8, (r - 1) & 1);
            const int kv0 = j * 32;
            const uint32_t stg = sb + s2 * SSTR;
#pragma unroll
            for (int u4 = 0; u4 < 4; u4++) {
                const int u = tid + u4 * 256;
                const int row = u >> 5, c = u & 31;
                cp16(stg + row * 576 + c * 16, &g_kint[(b * SEQ + kv0 + row) * 32 + c]);
            }
#pragma unroll
            for (int u4 = 0; u4 < 4; u4++) {
                const int u = tid + u4 * 256;
                const int row = u >> 3, c = u & 7;
                cp16(stg + OVS + row * 192 + c * 16,
                     &g_vint[((b * 128 + row) * 32 + (j >> 1)) * 16 + (j & 1) * 8 + c]);
            }
            if (tid < 8) cp16(stg + OMS + tid * 16, mb + kv0 + tid * 4);
            CPASYNC_MBAR_ARRIVE(fullb + s2 * 8);
        }

        // ---- consume tile it ----
        const int s = it & (RING - 1), rr = it >> 2;
        mbar_wait(fullb + s * 8, rr & 1);
        const char* Kp = smx + s * SSTR;
        const char* Vp = Kp + OVS;
        const float* ms = (const float*)(Kp + OMS);

        // S = Q K^T
        float sacc[4][4];
#pragma unroll
        for (int j2 = 0; j2 < 4; j2++)
#pragma unroll
            for (int i = 0; i < 4; i++) sacc[j2][i] = 0.f;
#pragma unroll
        for (int ks = 0; ks < 8; ks++) {
#pragma unroll
            for (int j2 = 0; j2 < 4; j2++) {
                const uint4 kb = *(const uint4*)(Kp + (j2 * 8 + g) * 576 + ks * 64 + t * 16);
                uint32_t bh[2] = {kb.x, kb.y};
                uint32_t bl[2] = {kb.z, kb.w};
                mma16816(sacc[j2], qah[ks], bh);
                mma16816(sacc[j2], qah[ks], bl);
                mma16816(sacc[j2], qal[ks], bh);
            }
        }

        // mask + online softmax
        float rmax0 = -INFINITY, rmax1 = -INFINITY;
#pragma unroll
        for (int j2 = 0; j2 < 4; j2++) {
            const float mva = ms[j2 * 8 + t * 2], mvb = ms[j2 * 8 + t * 2 + 1];
            sacc[j2][0] = mva * sacc[j2][0] + (1.f - mva) * MASK_VALUE;
            sacc[j2][1] = mvb * sacc[j2][1] + (1.f - mvb) * MASK_VALUE;
            sacc[j2][2] = mva * sacc[j2][2] + (1.f - mva) * MASK_VALUE;
            sacc[j2][3] = mvb * sacc[j2][3] + (1.f - mvb) * MASK_VALUE;
            rmax0 = fmaxf(rmax0, fmaxf(sacc[j2][0], sacc[j2][1]));
            rmax1 = fmaxf(rmax1, fmaxf(sacc[j2][2], sacc[j2][3]));
        }
#pragma unroll
        for (int off = 1; off <= 2; off <<= 1) {
            rmax0 = fmaxf(rmax0, __shfl_xor_sync(0xffffffffu, rmax0, off));
            rmax1 = fmaxf(rmax1, __shfl_xor_sync(0xffffffffu, rmax1, off));
        }
        const float mo0 = m0, mo1 = m1;
        const float mn0 = fmaxf(m0, rmax0), mn1 = fmaxf(m1, rmax1);
        const float a0 = ex2f((m0 - mn0) * LOG2E), a1 = ex2f((m1 - mn1) * LOG2E);
        float ps0 = 0.f, ps1 = 0.f;
#pragma unroll
        for (int j2 = 0; j2 < 4; j2++) {
            sacc[j2][0] = ex2f((sacc[j2][0] - mn0) * LOG2E);
            sacc[j2][1] = ex2f((sacc[j2][1] - mn0) * LOG2E);
            sacc[j2][2] = ex2f((sacc[j2][2] - mn1) * LOG2E);
            sacc[j2][3] = ex2f((sacc[j2][3] - mn1) * LOG2E);
            ps0 += sacc[j2][0] + sacc[j2][1];
            ps1 += sacc[j2][2] + sacc[j2][3];
        }
#pragma unroll
        for (int off = 1; off <= 2; off <<= 1) {
            ps0 += __shfl_xor_sync(0xffffffffu, ps0, off);
            ps1 += __shfl_xor_sync(0xffffffffu, ps1, off);
        }
        l0 = l0 * a0 + ps0; m0 = mn0;
        l1 = l1 * a1 + ps1; m1 = mn1;
        // rescale only if some row's max advanced (alpha exactly 1 otherwise)
        if (__any_sync(0xffffffffu, (mn0 > mo0) || (mn1 > mo1))) {
#pragma unroll
            for (int n = 0; n < 16; n++) {
                oacc[n][0] *= a0; oacc[n][1] *= a0;
                oacc[n][2] *= a1; oacc[n][3] *= a1;
            }
        }

        // O += P V
#pragma unroll
        for (int kk = 0; kk < 2; kk++) {
            const int j0 = 2 * kk, j1 = 2 * kk + 1;
            uint32_t pah[4], pal[4];
            split2(sacc[j0][0], sacc[j0][1], pah[0], pal[0]);
            split2(sacc[j0][2], sacc[j0][3], pah[1], pal[1]);
            split2(sacc[j1][0], sacc[j1][1], pah[2], pal[2]);
            split2(sacc[j1][2], sacc[j1][3], pah[3], pal[3]);
#pragma unroll
            for (int n = 0; n < 16; n++) {
                const uint4 vv = *(const uint4*)(Vp + (n * 8 + g) * 192 + kk * 64 + t * 16);
                uint32_t bh[2] = {vv.x, vv.y};
                uint32_t bl[2] = {vv.z, vv.w};
                mma16816(oacc[n], pah, bh);
                mma16816(oacc[n], pah, bl);
                mma16816(oacc[n], pal, bh);
            }
        }

        MBAR_ARRIVE(emptyb + s * 8);
    }

    // ---- epilogue ----
    const float i0 = (l0 > 0.f) ? (1.f / l0) : 0.f;
    const float i1 = (l1 > 0.f) ? (1.f / l1) : 0.f;
    float2* o2a = (float2*)(Outg + ((size_t)b * SEQ + q0 + rg) * DIM);
    float2* o2b = (float2*)(Outg + ((size_t)b * SEQ + q0 + rg + 8) * DIM);
#pragma unroll
    for (int n = 0; n < 16; n++) {
        o2a[n * 4 + t] = make_float2(oacc[n][0] * i0, oacc[n][1] * i0);
        o2b[n * 4 + t] = make_float2(oacc[n][2] * i1, oacc[n][3] * i1);
    }
}

// ---------------------------------------------------------------------------
extern "C" void kernel_launch(void* const* d_in, const int* in_sizes, int n_in,
                              void* d_out, int out_size) {
    (void)in_sizes; (void)n_in; (void)out_size;
    const float* query = (const float*)d_in[0];
    const float* key   = (const float*)d_in[1];
    const float* value = (const float*)d_in[2];
    const float* mask  = (const float*)d_in[3];
    const float* Wq    = (const float*)d_in[4];
    const float* Wk    = (const float*)d_in[5];
    float* out = (float*)d_out;

    cudaFuncSetAttribute(prep_kernel, cudaFuncAttributeMaxDynamicSharedMemorySize, PREP_SMEM);
    cudaFuncSetAttribute(attn_hmma, cudaFuncAttributeMaxDynamicSharedMemorySize, SM_TOTAL);

    prep_kernel<<<512, 256, PREP_SMEM>>>(query, key, Wq, Wk, value);
    attn_hmma<<<dim3(SEQ / 128, BATCH), 256, SM_TOTAL>>>(mask, out);
}